// round 12
// baseline (speedup 1.0000x reference)
#include <cuda_runtime.h>
#include <cuda_fp16.h>

#define NS    6
#define NC    64
#define HFD   44
#define WFD   80
#define HW    (HFD*WFD)       // 3520
#define ZD    16
#define YD    100
#define XD    100
#define NVOX  (XD*YD*ZD)      // 160000

// Scratch (no cudaMalloc allowed)
__device__ __align__(16) __half g_featT[NS*HW*NC];  // [s][h][w][c], fp16
__device__ float  g_M[NS][12];        // rows 0..2 of featpix_T_cams @ inv(cam0_T_camXs)
__device__ float  g_Zrow[NS][4];      // row 2 of inv(cam0_T_camXs)

// ---------------------------------------------------------------------------
// Matrix prep (device helper, run by spare threads of transpose block 0)
// ---------------------------------------------------------------------------
__device__ void prep_one(int s, const float* __restrict__ pix,
                         const float* __restrict__ c0x) {
    const float* K = pix + s * 16;
    const float* T = c0x + s * 16;

    float inv[4][4];
#pragma unroll
    for (int i = 0; i < 4; i++)
#pragma unroll
        for (int j = 0; j < 4; j++) inv[i][j] = 0.f;
#pragma unroll
    for (int i = 0; i < 3; i++)
#pragma unroll
        for (int j = 0; j < 3; j++) inv[i][j] = T[j*4 + i];   // R^T
#pragma unroll
    for (int i = 0; i < 3; i++) {
        float v = 0.f;
#pragma unroll
        for (int j = 0; j < 3; j++) v += T[j*4 + i] * T[j*4 + 3];
        inv[i][3] = -v;
    }
    inv[3][3] = 1.f;

    const float sx = (float)WFD / 640.0f;   // 0.125
    const float sy = (float)HFD / 352.0f;   // 0.125
    float FP[4][4];
#pragma unroll
    for (int j = 0; j < 4; j++) {
        FP[0][j] = sx * K[j];
        FP[1][j] = sy * K[4 + j];
        FP[2][j] = K[8 + j];
        FP[3][j] = K[12 + j];
    }

#pragma unroll
    for (int i = 0; i < 3; i++)
#pragma unroll
        for (int j = 0; j < 4; j++) {
            float v = 0.f;
#pragma unroll
            for (int k = 0; k < 4; k++) v += FP[i][k] * inv[k][j];
            g_M[s][i*4 + j] = v;
        }
#pragma unroll
    for (int j = 0; j < 4; j++) g_Zrow[s][j] = inv[2][j];
}

// ---------------------------------------------------------------------------
// Kernel 1: transpose [S,C,H,W] fp32 -> [S,H,W,C] fp16, vectorized.
// 256 threads, tile = 64 channels x 32 pixels.
// ---------------------------------------------------------------------------
__global__ void transpose_feat(const float* __restrict__ in,
                               const float* __restrict__ pix,
                               const float* __restrict__ c0x) {
    __shared__ float tile[64][33];
    const int s     = blockIdx.z;
    const int pBase = blockIdx.x * 32;
    const int tid   = threadIdx.x;

    if (blockIdx.x == 0 && blockIdx.z == 0 && tid < NS)
        prep_one(tid, pix, c0x);

    const float* ip = in + s * NC * HW;
#pragma unroll
    for (int k = 0; k < 2; k++) {
        const int idx = tid + k * 256;
        const int c   = idx >> 3;
        const int p4  = idx & 7;
        const float4 v = *reinterpret_cast<const float4*>(ip + c * HW + pBase + 4*p4);
        tile[c][4*p4 + 0] = v.x;
        tile[c][4*p4 + 1] = v.y;
        tile[c][4*p4 + 2] = v.z;
        tile[c][4*p4 + 3] = v.w;
    }
    __syncthreads();

    // pack: thread (pp = tid>>3, b = tid&7) -> pixel pBase+pp, channels [8b,8b+8)
    const int pp = tid >> 3;
    const int b  = tid & 7;
    uint4 u;
    unsigned* up = &u.x;
#pragma unroll
    for (int jj = 0; jj < 4; jj++) {
        __half2 h = __floats2half2_rn(tile[8*b + 2*jj][pp], tile[8*b + 2*jj + 1][pp]);
        up[jj] = *reinterpret_cast<unsigned*>(&h);
    }
    uint4* op = reinterpret_cast<uint4*>(g_featT + s * HW * NC);
    op[(pBase + pp) * 8 + b] = u;   // 512B contiguous per warp
}

// ---------------------------------------------------------------------------
// Kernel 2: project + bilinear sample + camera reduction
// Block: 512 threads, 64 voxels.
// Projection: warps 0..11 = (camera, half), lane = voxel; validity via ballot.
// Sampling:   warp = 4 voxels, lane>>3 = voxel, lane&7 = channel octet.
// ---------------------------------------------------------------------------
__device__ __forceinline__ void sample_cam4(const __half2* __restrict__ ft2,
                                            const int4 o, const uint4 wp,
                                            int e4, __half2 r[4]) {
    const uint4 a = *reinterpret_cast<const uint4*>(ft2 + o.x + e4);
    const uint4 b = *reinterpret_cast<const uint4*>(ft2 + o.y + e4);
    const uint4 c = *reinterpret_cast<const uint4*>(ft2 + o.z + e4);
    const uint4 d = *reinterpret_cast<const uint4*>(ft2 + o.w + e4);
    const __half2 w00 = *reinterpret_cast<const __half2*>(&wp.x);
    const __half2 w10 = *reinterpret_cast<const __half2*>(&wp.y);
    const __half2 w01 = *reinterpret_cast<const __half2*>(&wp.z);
    const __half2 w11 = *reinterpret_cast<const __half2*>(&wp.w);
    const unsigned* ap = &a.x; const unsigned* bp = &b.x;
    const unsigned* cp = &c.x; const unsigned* dp = &d.x;
#pragma unroll
    for (int j = 0; j < 4; j++) {
        __half2 t = __hmul2(w00, *reinterpret_cast<const __half2*>(&ap[j]));
        t = __hfma2(w10, *reinterpret_cast<const __half2*>(&bp[j]), t);
        t = __hfma2(w01, *reinterpret_cast<const __half2*>(&cp[j]), t);
        t = __hfma2(w11, *reinterpret_cast<const __half2*>(&dp[j]), t);
        r[j] = t;
    }
}

__global__ void __launch_bounds__(512) sample_kernel(float* __restrict__ out) {
    __shared__ int4     ent_o[64][7];   // stride 7 -> conflict-free stores (7 KB)
    __shared__ uint4    ent_w[64][7];   // (7 KB)
    __shared__ unsigned bal_sm[16];     // [g*6+s] voxel-validity ballots (padded)
    __shared__ __align__(16) float acc[64 * 64];   // rotated layout, 16 KB

    const int tid    = threadIdx.x;
    const int lane   = tid & 31;
    const int warp   = tid >> 5;
    const int ovBase = blockIdx.x * 64;

    // ---- Projection phase: warps 0..11, warp = (s = w>>1, g = w&1) ----
    if (warp < 2 * NS) {
        const int s   = warp >> 1;
        const int g   = warp & 1;
        const int vox = g * 32 + lane;

        const int ov  = ovBase + vox;
        const int ix  = ov / 1600;
        const int rem = ov - ix * 1600;
        const int iy  = rem >> 4;
        const int iz  = rem & 15;

        const float px = fmaf(0.8f, (float)ix + 0.5f, -40.0f);
        const float py = fmaf(0.8f, (float)iy + 0.5f, -40.0f);
        const float pz = fmaf(0.4f, (float)iz + 0.5f, -1.0f);

        const float* M  = g_M[s];    // warp-uniform
        const float* Zr = g_Zrow[s];
        const float xp = fmaf(M[0], px, fmaf(M[1], py, fmaf(M[2],  pz, M[3])));
        const float yp = fmaf(M[4], px, fmaf(M[5], py, fmaf(M[6],  pz, M[7])));
        const float zp = fmaf(M[8], px, fmaf(M[9], py, fmaf(M[10], pz, M[11])));
        const float zc = fmaf(Zr[0], px, fmaf(Zr[1], py, fmaf(Zr[2], pz, Zr[3])));

        const float rden = __fdividef(1.0f, fmaxf(zp, 1e-6f));
        const float xpix = xp * rden;
        const float ypix = yp * rden;

        const bool valid = (xpix > -0.5f) && (xpix < (float)WFD - 0.5f) &&
                           (ypix > -0.5f) && (ypix < (float)HFD - 0.5f) &&
                           (zc > 0.0f);
        const unsigned bal = __ballot_sync(0xffffffffu, valid);
        if (lane == 0) bal_sm[g * NS + s] = bal;

        if (valid) {
            const float x = xpix - 0.5f;
            const float y = ypix - 0.5f;
            const float fx0 = floorf(x), fy0 = floorf(y);
            const float wx1 = x - fx0,   wy1 = y - fy0;
            const float wx0 = 1.f - wx1, wy0 = 1.f - wy1;
            const int ix0 = (int)fx0, iy0 = (int)fy0;
            const bool vx0 = (ix0 >= 0), vy0 = (iy0 >= 0);
            const int cx0 = max(ix0, 0), cy0 = max(iy0, 0);
            const int cx1 = ix0 + 1,     cy1 = iy0 + 1;   // in-bounds given valid

            const int base = s * HFD;
            int4 o;
            o.x = ((base + cy0) * WFD + cx0) * (NC/2);
            o.y = ((base + cy0) * WFD + cx1) * (NC/2);
            o.z = ((base + cy1) * WFD + cx0) * (NC/2);
            o.w = ((base + cy1) * WFD + cx1) * (NC/2);
            ent_o[vox][s] = o;

            // fold 1/(1+1e-6) into the weights (fast path needs no epilogue mul;
            // slow path inherits a 1e-6 relative error -- negligible)
            const float inv1eps = 0.99999899999f;
            const float w00 = ((vx0 && vy0) ? wx0 * wy0 : 0.f) * inv1eps;
            const float w10 = (vy0 ? wx1 * wy0 : 0.f) * inv1eps;
            const float w01 = (vx0 ? wx0 * wy1 : 0.f) * inv1eps;
            const float w11 = (wx1 * wy1) * inv1eps;
            uint4 w;
            __half2 h;
            h = __float2half2_rn(w00); w.x = *reinterpret_cast<unsigned*>(&h);
            h = __float2half2_rn(w10); w.y = *reinterpret_cast<unsigned*>(&h);
            h = __float2half2_rn(w01); w.z = *reinterpret_cast<unsigned*>(&h);
            h = __float2half2_rn(w11); w.w = *reinterpret_cast<unsigned*>(&h);
            ent_w[vox][s] = w;
        }
    }
    __syncthreads();

    // ---- Sampling phase: warp processes its 4 voxels in one pass ----
    const int q  = lane >> 3;        // voxel within warp's group of 4
    const int e  = lane & 7;         // channel octet: channels [8e, 8e+8)
    const int e4 = e * 4;            // in half2 units
    const int v  = warp * 4 + q;     // per-lane voxel (0..63)
    const __half2* __restrict__ ft2 = reinterpret_cast<const __half2*>(g_featT);
    const __half2 h2zero = __float2half2_rn(0.f);

    const int gsel = v >> 5;
    const int vb   = v & 31;
    int m = 0;
#pragma unroll
    for (int s2 = 0; s2 < NS; s2++)
        m |= (int)((bal_sm[gsel * NS + s2] >> vb) & 1u) << s2;

    // rotated columns: channel c of voxel v lives at (c + 4*(v>>2) + 4*(v&3)) & 63
    const int colA = (8*e + 4*(v >> 2) + 4*q) & 63;
    const int colB = (colA + 4) & 63;
    float* accA = &acc[v * 64 + colA];
    float* accB = &acc[v * 64 + colB];

    if (__all_sync(0xffffffffu, (m & (m - 1)) == 0)) {
        // all 4 voxels have <= 1 camera (common case)
        float4 lo = make_float4(0.f, 0.f, 0.f, 0.f);
        float4 hi = make_float4(0.f, 0.f, 0.f, 0.f);
        if (m) {
            const int s = __ffs(m) - 1;
            __half2 r[4];
            sample_cam4(ft2, ent_o[v][s], ent_w[v][s], e4, r);
            const float2 f0 = __half22float2(r[0]);
            const float2 f1 = __half22float2(r[1]);
            const float2 f2 = __half22float2(r[2]);
            const float2 f3 = __half22float2(r[3]);
            lo = make_float4(f0.x, f0.y, f1.x, f1.y);
            hi = make_float4(f2.x, f2.y, f3.x, f3.y);
        }
        *reinterpret_cast<float4*>(accA) = lo;
        *reinterpret_cast<float4*>(accB) = hi;
    } else {
        float sum[8];
        __half2 cnt[4];
#pragma unroll
        for (int j = 0; j < 8; j++) sum[j] = 0.f;
#pragma unroll
        for (int j = 0; j < 4; j++) cnt[j] = h2zero;
        int mm = m;
        while (__any_sync(0xffffffffu, mm != 0)) {
            if (mm) {
                const int s = __ffs(mm) - 1;     // ascending -> deterministic
                mm &= mm - 1;
                __half2 r[4];
                sample_cam4(ft2, ent_o[v][s], ent_w[v][s], e4, r);
#pragma unroll
                for (int j = 0; j < 4; j++) {
                    const float2 f = __half22float2(r[j]);
                    sum[2*j]   += f.x;
                    sum[2*j+1] += f.y;
                    cnt[j] = __hadd2(cnt[j], __hne2(r[j], h2zero));
                }
            }
        }
        float4 lo, hi;
        float* lop = &lo.x; float* hip = &hi.x;
#pragma unroll
        for (int j = 0; j < 4; j++) {
            const float2 c = __half22float2(cnt[j]);
            float r0 = sum[2*j]   * __fdividef(1.0f, c.x + 1e-6f);
            float r1 = sum[2*j+1] * __fdividef(1.0f, c.y + 1e-6f);
            if (j < 2) { lop[2*j] = r0; lop[2*j+1] = r1; }
            else       { hip[2*(j-2)] = r0; hip[2*(j-2)+1] = r1; }
        }
        *reinterpret_cast<float4*>(accA) = lo;
        *reinterpret_cast<float4*>(accB) = hi;
    }
    __syncthreads();

    // ---- Write phase: conflict-free rotated reads + STG.128 ----
    // thread: v4 = tid&7 (voxel quad within group), c = tid>>3 (0..63); 2 groups.
    {
        const int v4 = tid & 7;
        const int c  = tid >> 3;
#pragma unroll
        for (int g = 0; g < 2; g++) {
            const int vb0 = g * 32 + 4 * v4;
            float4 r;
            r.x = acc[(vb0 + 0) * 64 + ((c + 4*((vb0+0) >> 2) + 4*((vb0+0) & 3)) & 63)];
            r.y = acc[(vb0 + 1) * 64 + ((c + 4*((vb0+1) >> 2) + 4*((vb0+1) & 3)) & 63)];
            r.z = acc[(vb0 + 2) * 64 + ((c + 4*((vb0+2) >> 2) + 4*((vb0+2) & 3)) & 63)];
            r.w = acc[(vb0 + 3) * 64 + ((c + 4*((vb0+3) >> 2) + 4*((vb0+3) & 3)) & 63)];
            *reinterpret_cast<float4*>(out + c * NVOX + ovBase + vb0) = r;
        }
    }
}

// ---------------------------------------------------------------------------
extern "C" void kernel_launch(void* const* d_in, const int* in_sizes, int n_in,
                              void* d_out, int out_size) {
    int fi = 0;
    for (int i = 0; i < n_in; i++)
        if (in_sizes[i] == NS * NC * HFD * WFD) { fi = i; break; }
    int mi0 = -1, mi1 = -1;
    for (int i = 0; i < n_in; i++) {
        if (i == fi) continue;
        if (mi0 < 0) mi0 = i; else if (mi1 < 0) mi1 = i;
    }
    const float* features = (const float*)d_in[fi];
    const float* pix      = (const float*)d_in[mi0];   // pix_T_cams
    const float* c0x      = (const float*)d_in[mi1];   // cam0_T_camXs

    dim3 tg(HW / 32, 1, NS);
    transpose_feat<<<tg, 256>>>(features, pix, c0x);

    sample_kernel<<<NVOX / 64, 512>>>((float*)d_out);
}

// round 13
// speedup vs baseline: 1.2222x; 1.2222x over previous
#include <cuda_runtime.h>
#include <cuda_fp16.h>

#define NS    6
#define NC    64
#define HFD   44
#define WFD   80
#define HW    (HFD*WFD)       // 3520
#define ZD    16
#define YD    100
#define XD    100
#define NVOX  (XD*YD*ZD)      // 160000

// Scratch (no cudaMalloc allowed)
__device__ __align__(16) __half g_featT[NS*HW*NC];  // [s][h][w][c], fp16
__device__ float  g_M[NS][12];        // rows 0..2 of featpix_T_cams @ inv(cam0_T_camXs)
__device__ float  g_Zrow[NS][4];      // row 2 of inv(cam0_T_camXs)

// ---------------------------------------------------------------------------
// Matrix prep (device helper, run by spare threads of transpose block 0)
// ---------------------------------------------------------------------------
__device__ void prep_one(int s, const float* __restrict__ pix,
                         const float* __restrict__ c0x) {
    const float* K = pix + s * 16;
    const float* T = c0x + s * 16;

    float inv[4][4];
#pragma unroll
    for (int i = 0; i < 4; i++)
#pragma unroll
        for (int j = 0; j < 4; j++) inv[i][j] = 0.f;
#pragma unroll
    for (int i = 0; i < 3; i++)
#pragma unroll
        for (int j = 0; j < 3; j++) inv[i][j] = T[j*4 + i];   // R^T
#pragma unroll
    for (int i = 0; i < 3; i++) {
        float v = 0.f;
#pragma unroll
        for (int j = 0; j < 3; j++) v += T[j*4 + i] * T[j*4 + 3];
        inv[i][3] = -v;
    }
    inv[3][3] = 1.f;

    const float sx = (float)WFD / 640.0f;   // 0.125
    const float sy = (float)HFD / 352.0f;   // 0.125
    float FP[4][4];
#pragma unroll
    for (int j = 0; j < 4; j++) {
        FP[0][j] = sx * K[j];
        FP[1][j] = sy * K[4 + j];
        FP[2][j] = K[8 + j];
        FP[3][j] = K[12 + j];
    }

#pragma unroll
    for (int i = 0; i < 3; i++)
#pragma unroll
        for (int j = 0; j < 4; j++) {
            float v = 0.f;
#pragma unroll
            for (int k = 0; k < 4; k++) v += FP[i][k] * inv[k][j];
            g_M[s][i*4 + j] = v;
        }
#pragma unroll
    for (int j = 0; j < 4; j++) g_Zrow[s][j] = inv[2][j];
}

// ---------------------------------------------------------------------------
// Kernel 1: transpose [S,C,H,W] fp32 -> [S,H,W,C] fp16, vectorized.
// 256 threads, tile = 64 channels x 32 pixels.
// ---------------------------------------------------------------------------
__global__ void transpose_feat(const float* __restrict__ in,
                               const float* __restrict__ pix,
                               const float* __restrict__ c0x) {
    __shared__ float tile[64][33];
    const int s     = blockIdx.z;
    const int pBase = blockIdx.x * 32;
    const int tid   = threadIdx.x;

    if (blockIdx.x == 0 && blockIdx.z == 0 && tid < NS)
        prep_one(tid, pix, c0x);

    const float* ip = in + s * NC * HW;
#pragma unroll
    for (int k = 0; k < 2; k++) {
        const int idx = tid + k * 256;
        const int c   = idx >> 3;
        const int p4  = idx & 7;
        const float4 v = *reinterpret_cast<const float4*>(ip + c * HW + pBase + 4*p4);
        tile[c][4*p4 + 0] = v.x;
        tile[c][4*p4 + 1] = v.y;
        tile[c][4*p4 + 2] = v.z;
        tile[c][4*p4 + 3] = v.w;
    }
    __syncthreads();

    // pack: thread (pp = tid>>3, b = tid&7) -> pixel pBase+pp, channels [8b,8b+8)
    const int pp = tid >> 3;
    const int b  = tid & 7;
    uint4 u;
    unsigned* up = &u.x;
#pragma unroll
    for (int jj = 0; jj < 4; jj++) {
        __half2 h = __floats2half2_rn(tile[8*b + 2*jj][pp], tile[8*b + 2*jj + 1][pp]);
        up[jj] = *reinterpret_cast<unsigned*>(&h);
    }
    uint4* op = reinterpret_cast<uint4*>(g_featT + s * HW * NC);
    op[(pBase + pp) * 8 + b] = u;   // 512B contiguous per warp
}

// ---------------------------------------------------------------------------
// Kernel 2: project + bilinear sample + camera reduction
// Block: 256 threads, 32 voxels (R10 configuration — best measured).
// Projection: warp = camera (6 warps), lane = voxel; validity via ballot.
// Sampling:   warp = 4 voxels, lane>>3 = voxel, lane&7 = channel octet.
// ---------------------------------------------------------------------------
__device__ __forceinline__ void sample_cam4(const __half2* __restrict__ ft2,
                                            const int4 o, const uint4 wp,
                                            int e4, __half2 r[4]) {
    const uint4 a = *reinterpret_cast<const uint4*>(ft2 + o.x + e4);
    const uint4 b = *reinterpret_cast<const uint4*>(ft2 + o.y + e4);
    const uint4 c = *reinterpret_cast<const uint4*>(ft2 + o.z + e4);
    const uint4 d = *reinterpret_cast<const uint4*>(ft2 + o.w + e4);
    const __half2 w00 = *reinterpret_cast<const __half2*>(&wp.x);
    const __half2 w10 = *reinterpret_cast<const __half2*>(&wp.y);
    const __half2 w01 = *reinterpret_cast<const __half2*>(&wp.z);
    const __half2 w11 = *reinterpret_cast<const __half2*>(&wp.w);
    const unsigned* ap = &a.x; const unsigned* bp = &b.x;
    const unsigned* cp = &c.x; const unsigned* dp = &d.x;
#pragma unroll
    for (int j = 0; j < 4; j++) {
        __half2 t = __hmul2(w00, *reinterpret_cast<const __half2*>(&ap[j]));
        t = __hfma2(w10, *reinterpret_cast<const __half2*>(&bp[j]), t);
        t = __hfma2(w01, *reinterpret_cast<const __half2*>(&cp[j]), t);
        t = __hfma2(w11, *reinterpret_cast<const __half2*>(&dp[j]), t);
        r[j] = t;
    }
}

__global__ void __launch_bounds__(256) sample_kernel(float* __restrict__ out) {
    __shared__ int4     ent_o[32][7];   // stride 7 -> conflict-free stores (3.5 KB)
    __shared__ uint4    ent_w[32][7];   // (3.5 KB)
    __shared__ unsigned bal_sm[8];      // per-camera voxel validity (padded to 32B)
    __shared__ __align__(16) float acc[32 * 64];   // rotated layout, 8 KB

    const int tid    = threadIdx.x;
    const int lane   = tid & 31;
    const int warp   = tid >> 5;
    const int ovBase = blockIdx.x * 32;

    // ---- Projection phase: warp = camera s (warps 0..5), lane = voxel ----
    if (warp < NS) {
        const int s   = warp;
        const int vox = lane;

        const int ov  = ovBase + vox;
        const int ix  = ov / 1600;
        const int rem = ov - ix * 1600;
        const int iy  = rem >> 4;
        const int iz  = rem & 15;

        const float px = fmaf(0.8f, (float)ix + 0.5f, -40.0f);
        const float py = fmaf(0.8f, (float)iy + 0.5f, -40.0f);
        const float pz = fmaf(0.4f, (float)iz + 0.5f, -1.0f);

        const float* M  = g_M[s];    // warp-uniform
        const float* Zr = g_Zrow[s];
        const float xp = fmaf(M[0], px, fmaf(M[1], py, fmaf(M[2],  pz, M[3])));
        const float yp = fmaf(M[4], px, fmaf(M[5], py, fmaf(M[6],  pz, M[7])));
        const float zp = fmaf(M[8], px, fmaf(M[9], py, fmaf(M[10], pz, M[11])));
        const float zc = fmaf(Zr[0], px, fmaf(Zr[1], py, fmaf(Zr[2], pz, Zr[3])));

        const float rden = __fdividef(1.0f, fmaxf(zp, 1e-6f));
        const float xpix = xp * rden;
        const float ypix = yp * rden;

        const bool valid = (xpix > -0.5f) && (xpix < (float)WFD - 0.5f) &&
                           (ypix > -0.5f) && (ypix < (float)HFD - 0.5f) &&
                           (zc > 0.0f);
        const unsigned bal = __ballot_sync(0xffffffffu, valid);
        if (lane == 0) bal_sm[s] = bal;

        if (valid) {
            const float x = xpix - 0.5f;
            const float y = ypix - 0.5f;
            const float fx0 = floorf(x), fy0 = floorf(y);
            const float wx1 = x - fx0,   wy1 = y - fy0;
            const float wx0 = 1.f - wx1, wy0 = 1.f - wy1;
            const int ix0 = (int)fx0, iy0 = (int)fy0;
            const bool vx0 = (ix0 >= 0), vy0 = (iy0 >= 0);
            const int cx0 = max(ix0, 0), cy0 = max(iy0, 0);
            const int cx1 = ix0 + 1,     cy1 = iy0 + 1;   // in-bounds given valid

            const int base = s * HFD;
            int4 o;
            o.x = ((base + cy0) * WFD + cx0) * (NC/2);
            o.y = ((base + cy0) * WFD + cx1) * (NC/2);
            o.z = ((base + cy1) * WFD + cx0) * (NC/2);
            o.w = ((base + cy1) * WFD + cx1) * (NC/2);
            ent_o[vox][s] = o;

            // fold 1/(1+1e-6) into the weights (fast path needs no epilogue mul;
            // slow path inherits a 1e-6 relative error -- negligible)
            const float inv1eps = 0.99999899999f;
            const float w00 = ((vx0 && vy0) ? wx0 * wy0 : 0.f) * inv1eps;
            const float w10 = (vy0 ? wx1 * wy0 : 0.f) * inv1eps;
            const float w01 = (vx0 ? wx0 * wy1 : 0.f) * inv1eps;
            const float w11 = (wx1 * wy1) * inv1eps;
            uint4 w;
            __half2 h;
            h = __float2half2_rn(w00); w.x = *reinterpret_cast<unsigned*>(&h);
            h = __float2half2_rn(w10); w.y = *reinterpret_cast<unsigned*>(&h);
            h = __float2half2_rn(w01); w.z = *reinterpret_cast<unsigned*>(&h);
            h = __float2half2_rn(w11); w.w = *reinterpret_cast<unsigned*>(&h);
            ent_w[vox][s] = w;
        }
    }
    __syncthreads();

    // ---- Sampling phase: warp processes its 4 voxels in one pass ----
    const int q  = lane >> 3;        // voxel within warp's group of 4
    const int e  = lane & 7;         // channel octet: channels [8e, 8e+8)
    const int e4 = e * 4;            // in half2 units
    const int v  = warp * 4 + q;     // per-lane voxel
    const __half2* __restrict__ ft2 = reinterpret_cast<const __half2*>(g_featT);
    const __half2 h2zero = __float2half2_rn(0.f);

    int m = 0;
#pragma unroll
    for (int s2 = 0; s2 < NS; s2++)
        m |= (int)((bal_sm[s2] >> v) & 1u) << s2;

    // rotated columns: channel c of voxel v lives at (c + 4*(v>>2) + 4*(v&3)) & 63
    const int colA = (8*e + 4*warp + 4*q) & 63;
    const int colB = (colA + 4) & 63;
    float* accA = &acc[v * 64 + colA];
    float* accB = &acc[v * 64 + colB];

    if (__all_sync(0xffffffffu, (m & (m - 1)) == 0)) {
        // all 4 voxels have <= 1 camera (common case)
        float4 lo = make_float4(0.f, 0.f, 0.f, 0.f);
        float4 hi = make_float4(0.f, 0.f, 0.f, 0.f);
        if (m) {
            const int s = __ffs(m) - 1;
            __half2 r[4];
            sample_cam4(ft2, ent_o[v][s], ent_w[v][s], e4, r);
            const float2 f0 = __half22float2(r[0]);
            const float2 f1 = __half22float2(r[1]);
            const float2 f2 = __half22float2(r[2]);
            const float2 f3 = __half22float2(r[3]);
            lo = make_float4(f0.x, f0.y, f1.x, f1.y);
            hi = make_float4(f2.x, f2.y, f3.x, f3.y);
        }
        *reinterpret_cast<float4*>(accA) = lo;
        *reinterpret_cast<float4*>(accB) = hi;
    } else {
        float sum[8];
        __half2 cnt[4];
#pragma unroll
        for (int j = 0; j < 8; j++) sum[j] = 0.f;
#pragma unroll
        for (int j = 0; j < 4; j++) cnt[j] = h2zero;
        int mm = m;
        while (__any_sync(0xffffffffu, mm != 0)) {
            if (mm) {
                const int s = __ffs(mm) - 1;     // ascending -> deterministic
                mm &= mm - 1;
                __half2 r[4];
                sample_cam4(ft2, ent_o[v][s], ent_w[v][s], e4, r);
#pragma unroll
                for (int j = 0; j < 4; j++) {
                    const float2 f = __half22float2(r[j]);
                    sum[2*j]   += f.x;
                    sum[2*j+1] += f.y;
                    cnt[j] = __hadd2(cnt[j], __hne2(r[j], h2zero));
                }
            }
        }
        float4 lo, hi;
        float* lop = &lo.x; float* hip = &hi.x;
#pragma unroll
        for (int j = 0; j < 4; j++) {
            const float2 c = __half22float2(cnt[j]);
            float r0 = sum[2*j]   * __fdividef(1.0f, c.x + 1e-6f);
            float r1 = sum[2*j+1] * __fdividef(1.0f, c.y + 1e-6f);
            if (j < 2) { lop[2*j] = r0; lop[2*j+1] = r1; }
            else       { hip[2*(j-2)] = r0; hip[2*(j-2)+1] = r1; }
        }
        *reinterpret_cast<float4*>(accA) = lo;
        *reinterpret_cast<float4*>(accB) = hi;
    }
    __syncthreads();

    // ---- Write phase: conflict-free rotated reads + STG.128 ----
#pragma unroll
    for (int t = 0; t < 2; t++) {
        const int v4 = tid & 7;
        const int c  = (tid >> 3) + t * 32;
        float4 r;
        r.x = acc[(4*v4 + 0) * 64 + ((c + 4*v4 +  0) & 63)];
        r.y = acc[(4*v4 + 1) * 64 + ((c + 4*v4 +  4) & 63)];
        r.z = acc[(4*v4 + 2) * 64 + ((c + 4*v4 +  8) & 63)];
        r.w = acc[(4*v4 + 3) * 64 + ((c + 4*v4 + 12) & 63)];
        *reinterpret_cast<float4*>(out + c * NVOX + ovBase + 4*v4) = r;
    }
}

// ---------------------------------------------------------------------------
extern "C" void kernel_launch(void* const* d_in, const int* in_sizes, int n_in,
                              void* d_out, int out_size) {
    int fi = 0;
    for (int i = 0; i < n_in; i++)
        if (in_sizes[i] == NS * NC * HFD * WFD) { fi = i; break; }
    int mi0 = -1, mi1 = -1;
    for (int i = 0; i < n_in; i++) {
        if (i == fi) continue;
        if (mi0 < 0) mi0 = i; else if (mi1 < 0) mi1 = i;
    }
    const float* features = (const float*)d_in[fi];
    const float* pix      = (const float*)d_in[mi0];   // pix_T_cams
    const float* c0x      = (const float*)d_in[mi1];   // cam0_T_camXs

    dim3 tg(HW / 32, 1, NS);
    transpose_feat<<<tg, 256>>>(features, pix, c0x);

    sample_kernel<<<NVOX / 32, 256>>>((float*)d_out);
}